// round 11
// baseline (speedup 1.0000x reference)
#include <cuda_runtime.h>

// HMLoss: 4-region histogram-matching L1 loss, H=W=2048.
// R11: redundant per-block table build made integer-exact and latency-flat:
//   - unnormalized integer cumsums; CDF comparisons via u64 cross-products
//     (cs_cum*tott vs ct_cum*tots) -> zero FDIV, zero scan rounding
//   - two-level warp scan (8 independent 5-shfl segment scans + register carry)
//   - binary lower-bound search on integers (== linear first-match, monotone)
// Hist and loss bodies unchanged (proven).

#define NQ    1048576   // (2048*2048)/4
#define NB    256
#define NHIST 24

__device__ unsigned int g_hist[NHIST * NB];   // zeroed at load; self-cleaning
__device__ double       g_acc;
__device__ unsigned int g_ticket;

#define LOSS_GRID 592

// Packed label LUTs (labels 0..18).
// A (mask_A): low16 = src hist base + 1 (0 = unmasked), bit16 = (label==11)
// B (mask_B): low16 = tar hist base + 1 for hair/eye (0 = none), bit16 = in tar face set
__constant__ int c_lutA[32] = {
    0, 1, 3073, 4609, 3073, 4609, 0,
    1, 1, 0, 1, 1 | (1 << 16), 0, 0,
    1, 0, 0, 1537, 0,
    0,0,0,0,0,0,0,0,0,0,0,0,0
};
__constant__ int c_lutB[32] = {
    0, (1<<16), 3841, 5377, 3841, 5377, 0,
    (1<<16), (1<<16), 0, (1<<16), 0, 0, 0,
    (1<<16), 0, 0, 2305, 0,
    0,0,0,0,0,0,0,0,0,0,0,0,0
};

// floor for x in [0, 2^23): round-toward-zero add of 2^23, take mantissa bits.
__device__ __forceinline__ int floor_pos(float x) {
    return __float_as_int(__fadd_rz(x, 8388608.0f)) & 0x7FFFFF;
}
// saturate((x+1)/2)
__device__ __forceinline__ float sat01(float x) {
    return __saturatef(fmaf(x, 0.5f, 0.5f));
}

// ---------------------------------------------------------------- K1: histograms
__device__ __forceinline__ void hist_px(int la, int lb,
                                        float fa, float fb, float fc,
                                        float ra, float rb, float rc,
                                        const int* lutA, const int* lutB,
                                        unsigned int* sh)
{
    int da = lutA[la];
    int db = lutB[lb];

    int sbase = (da & 0xFFFF) - 1;
    if (sbase >= 0) {
        int b0 = min(floor_pos(sat01(fa) * 256.0f), 255);
        int b1 = min(floor_pos(sat01(fb) * 256.0f), 255);
        int b2 = min(floor_pos(sat01(fc) * 256.0f), 255);
        atomicAdd(&sh[sbase          + b0], 1u);
        atomicAdd(&sh[sbase +     NB + b1], 1u);
        atomicAdd(&sh[sbase + 2 * NB + b2], 1u);
    }

    int faceval = ((da >> 16) & 1) + ((db >> 16) & 1);
    int tbase = (db & 0xFFFF) - 1;
    if ((faceval | (tbase + 1)) != 0) {
        float scale = (faceval == 2) ? 512.0f : 256.0f;   // faceval==2 implies tbase<0
        int b0 = min(floor_pos(sat01(ra) * scale), 255);
        int b1 = min(floor_pos(sat01(rb) * scale), 255);
        int b2 = min(floor_pos(sat01(rc) * scale), 255);
        if (faceval > 0) {
            atomicAdd(&sh[3 * NB          + b0], 1u);
            atomicAdd(&sh[3 * NB +     NB + b1], 1u);
            atomicAdd(&sh[3 * NB + 2 * NB + b2], 1u);
        }
        if (tbase >= 0) {
            atomicAdd(&sh[tbase          + b0], 1u);
            atomicAdd(&sh[tbase +     NB + b1], 1u);
            atomicAdd(&sh[tbase + 2 * NB + b2], 1u);
        }
    }
}

__global__ void __launch_bounds__(512, 2) hist_kernel(
    const float4* __restrict__ fake, const float4* __restrict__ refb,
    const int4* __restrict__ ma, const int4* __restrict__ mb)
{
    __shared__ unsigned int sh[NHIST * NB];
    __shared__ int lutA[32], lutB[32];
    for (int i = threadIdx.x; i < NHIST * NB; i += 512) sh[i] = 0u;
    if (threadIdx.x < 32) { lutA[threadIdx.x] = c_lutA[threadIdx.x];
                            lutB[threadIdx.x] = c_lutB[threadIdx.x]; }
    __syncthreads();

    int stride = gridDim.x * 512;
    for (int q = blockIdx.x * 512 + threadIdx.x; q < NQ; q += stride) {
        int4   a4 = ma[q],  b4 = mb[q];
        float4 f0 = fake[q], f1 = fake[q + NQ], f2 = fake[q + 2 * NQ];
        float4 r0 = refb[q], r1 = refb[q + NQ], r2 = refb[q + 2 * NQ];
        hist_px(a4.x, b4.x, f0.x, f1.x, f2.x, r0.x, r1.x, r2.x, lutA, lutB, sh);
        hist_px(a4.y, b4.y, f0.y, f1.y, f2.y, r0.y, r1.y, r2.y, lutA, lutB, sh);
        hist_px(a4.z, b4.z, f0.z, f1.z, f2.z, r0.z, r1.z, r2.z, lutA, lutB, sh);
        hist_px(a4.w, b4.w, f0.w, f1.w, f2.w, r0.w, r1.w, r2.w, lutA, lutB, sh);
    }
    __syncthreads();
    for (int i = threadIdx.x; i < NHIST * NB; i += 512) {
        unsigned v = sh[i];
        if (v) atomicAdd(&g_hist[i], v);
    }
}

// ---------------------------------------------------------------- K2: tables + loss
__device__ __forceinline__ float loss_px(int la, float fa, float fb, float fc,
                                         const int* lutA, const float* tbl)
{
    int sbase = ((lutA[la] & 0xFFFF) - 1) >> 1;   // src hist base/2 == region*3*NB
    float s = 0.0f;
    if (sbase >= 0) {
        const float* tb = tbl + sbase;
        float v0 = sat01(fa) * 255.0f;
        float v1 = sat01(fb) * 255.0f;
        float v2 = sat01(fc) * 255.0f;
        int i0 = min(floor_pos(v0), 255);
        int i1 = min(floor_pos(v1), 255);
        int i2 = min(floor_pos(v2), 255);
        s = fabsf(v0 - tb[i0]) + fabsf(v1 - tb[NB + i1]) + fabsf(v2 - tb[2 * NB + i2]);
    }
    return s;
}

__global__ void __launch_bounds__(256) table_loss_kernel(
    const float4* __restrict__ fake, const int4* __restrict__ ma, float* out)
{
    // smA: src integer cumsums, then (in-place) float tables; smB: tar cumsums
    __shared__ unsigned smA[12 * NB];
    __shared__ unsigned smB[12 * NB];
    __shared__ unsigned s_tots[12], s_tott[12];
    __shared__ int lutA[32];
    __shared__ float wsum[8];
    __shared__ int s_last;

    const int tid  = threadIdx.x;
    const int lane = tid & 31;
    const int wid  = tid >> 5;     // 8 warps

    if (tid < 32) lutA[tid] = c_lutA[tid];

    // ---- phase A: 24 integer cumsums, warp-per-(table,side), two-level scan
    #pragma unroll
    for (int round = 0; round < 3; round++) {
        int task = wid + round * 8;             // 0..23
        int rc = task >> 1, side = task & 1;    // rc = region*3 + c
        int region = rc / 3, c = rc - region * 3;
        int hbase = (region * 6 + side * 3 + c) * NB;

        unsigned v[8];
        #pragma unroll
        for (int k = 0; k < 8; k++)
            v[k] = g_hist[hbase + k * 32 + lane];      // coalesced

        // 8 independent 5-shfl inclusive scans (depth 5, pipelined)
        #pragma unroll
        for (int k = 0; k < 8; k++) {
            unsigned x = v[k];
            #pragma unroll
            for (int off = 1; off < 32; off <<= 1) {
                unsigned y = __shfl_up_sync(0xffffffffu, x, off);
                if (lane >= off) x += y;
            }
            v[k] = x;
        }
        unsigned seg[8];
        #pragma unroll
        for (int k = 0; k < 8; k++)
            seg[k] = __shfl_sync(0xffffffffu, v[k], 31);

        unsigned* dst = (side ? smB : smA) + rc * NB;
        unsigned carry = 0;
        #pragma unroll
        for (int k = 0; k < 8; k++) {
            dst[k * 32 + lane] = v[k] + carry;
            carry += seg[k];
        }
        if (lane == 0) {
            if (side) s_tott[rc] = carry; else s_tots[rc] = carry;
        }
    }
    __syncthreads();

    // ---- phase B: tables via exact integer binary lower-bound.
    // cd[i] >= ca[j]  <=>  cs_cum[i]*tott >= ct_cum[j]*tots   (u64, exact)
    #pragma unroll
    for (int r = 0; r < 12; r++) {
        const unsigned* ca = smB + r * NB;
        unsigned long long tots = s_tots[r];
        unsigned long long lhs  = (unsigned long long)smA[r * NB + tid] * s_tott[r];
        int lo = 1, hi = 255;
        #pragma unroll
        for (int s = 0; s < 8; s++) {
            int mid = (lo + hi) >> 1;
            if ((unsigned long long)ca[mid] * tots >= lhs) hi = mid; else lo = mid + 1;
        }
        bool found = (lhs >= (unsigned long long)ca[lo - 1] * tots)
                  && (lhs <= (unsigned long long)ca[lo]     * tots);
        int t = found ? lo : tid;
        if (tid == 0)   t = 0;
        if (tid == 255) t = 255;
        ((float*)smA)[r * NB + tid] = (float)t;   // in-place: only this thread read it
    }
    __syncthreads();

    // ---- phase C: loss (proven body); tables live in smA as float
    const float* tbl = (const float*)smA;
    float acc = 0.0f;
    int stride = gridDim.x * 256;
    for (int q = blockIdx.x * 256 + tid; q < NQ; q += stride) {
        int4   a4 = ma[q];
        float4 f0 = fake[q], f1 = fake[q + NQ], f2 = fake[q + 2 * NQ];
        acc += loss_px(a4.x, f0.x, f1.x, f2.x, lutA, tbl);
        acc += loss_px(a4.y, f0.y, f1.y, f2.y, lutA, tbl);
        acc += loss_px(a4.z, f0.z, f1.z, f2.z, lutA, tbl);
        acc += loss_px(a4.w, f0.w, f1.w, f2.w, lutA, tbl);
    }

    #pragma unroll
    for (int off = 16; off > 0; off >>= 1)
        acc += __shfl_down_sync(0xffffffffu, acc, off);
    if (lane == 0) wsum[wid] = acc;
    __syncthreads();
    if (tid == 0) {
        float s = 0.0f;
        #pragma unroll
        for (int i = 0; i < 8; i++) s += wsum[i];
        atomicAdd(&g_acc, (double)s);
        __threadfence();
        unsigned t = atomicAdd(&g_ticket, 1u);
        s_last = (t == (unsigned)(gridDim.x - 1)) ? 1 : 0;
    }
    __syncthreads();

    // ---- last block: finalize + reset global state (ticket full => all reads done)
    if (s_last) {
        for (int i = tid; i < NHIST * NB; i += 256) g_hist[i] = 0u;
        if (tid == 0) {
            double total = *((volatile double*)&g_acc);
            out[0] = (float)(total * (0.1 / 12582912.0));  // 0.1/(3*H*W)
            g_acc = 0.0;
            g_ticket = 0u;
        }
    }
}

// ---------------------------------------------------------------- launch
extern "C" void kernel_launch(void* const* d_in, const int* in_sizes, int n_in,
                              void* d_out, int out_size)
{
    (void)in_sizes; (void)n_in; (void)out_size;
    const float4* fake = (const float4*)d_in[0];
    const float4* refb = (const float4*)d_in[1];
    const int4*   ma   = (const int4*)d_in[2];
    const int4*   mb   = (const int4*)d_in[3];
    float* out = (float*)d_out;

    hist_kernel      <<<296, 512>>>(fake, refb, ma, mb);
    table_loss_kernel<<<LOSS_GRID, 256>>>(fake, ma, out);
}

// round 12
// speedup vs baseline: 1.0625x; 1.0625x over previous
#include <cuda_runtime.h>

// HMLoss: 4-region histogram-matching L1 loss, H=W=2048.
// R12: tables built ONCE in hist_kernel's tail (last-to-flush block, ticket),
// on L2-hot g_hist, using the R11 integer-exact warp build (u64 cross-product
// comparisons). K2 reverts to the pure proven loss kernel (12KB smem, 29 regs).
// R10/R11 showed per-block redundant table builds cost ~11us regardless of
// arithmetic -- structural, so pay it once (~3us serial tail) instead of 592x.

#define NQ    1048576   // (2048*2048)/4
#define NB    256
#define NHIST 24

__device__ unsigned int g_hist[NHIST * NB];   // zeroed at load; self-cleaning
__device__ float        g_tables[12 * NB];
__device__ double       g_acc;
__device__ unsigned int g_tick1, g_tick2;

#define LOSS_GRID 592

// Packed label LUTs (labels 0..18).
// A (mask_A): low16 = src hist base + 1 (0 = unmasked), bit16 = (label==11)
// B (mask_B): low16 = tar hist base + 1 for hair/eye (0 = none), bit16 = in tar face set
__constant__ int c_lutA[32] = {
    0, 1, 3073, 4609, 3073, 4609, 0,
    1, 1, 0, 1, 1 | (1 << 16), 0, 0,
    1, 0, 0, 1537, 0,
    0,0,0,0,0,0,0,0,0,0,0,0,0
};
__constant__ int c_lutB[32] = {
    0, (1<<16), 3841, 5377, 3841, 5377, 0,
    (1<<16), (1<<16), 0, (1<<16), 0, 0, 0,
    (1<<16), 0, 0, 2305, 0,
    0,0,0,0,0,0,0,0,0,0,0,0,0
};

// floor for x in [0, 2^23): round-toward-zero add of 2^23, take mantissa bits.
__device__ __forceinline__ int floor_pos(float x) {
    return __float_as_int(__fadd_rz(x, 8388608.0f)) & 0x7FFFFF;
}
// saturate((x+1)/2)
__device__ __forceinline__ float sat01(float x) {
    return __saturatef(fmaf(x, 0.5f, 0.5f));
}

// ---------------------------------------------------------------- K1: histograms (+ table tail)
__device__ __forceinline__ void hist_px(int la, int lb,
                                        float fa, float fb, float fc,
                                        float ra, float rb, float rc,
                                        const int* lutA, const int* lutB,
                                        unsigned int* sh)
{
    int da = lutA[la];
    int db = lutB[lb];

    int sbase = (da & 0xFFFF) - 1;
    if (sbase >= 0) {
        int b0 = min(floor_pos(sat01(fa) * 256.0f), 255);
        int b1 = min(floor_pos(sat01(fb) * 256.0f), 255);
        int b2 = min(floor_pos(sat01(fc) * 256.0f), 255);
        atomicAdd(&sh[sbase          + b0], 1u);
        atomicAdd(&sh[sbase +     NB + b1], 1u);
        atomicAdd(&sh[sbase + 2 * NB + b2], 1u);
    }

    int faceval = ((da >> 16) & 1) + ((db >> 16) & 1);
    int tbase = (db & 0xFFFF) - 1;
    if ((faceval | (tbase + 1)) != 0) {
        float scale = (faceval == 2) ? 512.0f : 256.0f;   // faceval==2 implies tbase<0
        int b0 = min(floor_pos(sat01(ra) * scale), 255);
        int b1 = min(floor_pos(sat01(rb) * scale), 255);
        int b2 = min(floor_pos(sat01(rc) * scale), 255);
        if (faceval > 0) {
            atomicAdd(&sh[3 * NB          + b0], 1u);
            atomicAdd(&sh[3 * NB +     NB + b1], 1u);
            atomicAdd(&sh[3 * NB + 2 * NB + b2], 1u);
        }
        if (tbase >= 0) {
            atomicAdd(&sh[tbase          + b0], 1u);
            atomicAdd(&sh[tbase +     NB + b1], 1u);
            atomicAdd(&sh[tbase + 2 * NB + b2], 1u);
        }
    }
}

__global__ void __launch_bounds__(512, 2) hist_kernel(
    const float4* __restrict__ fake, const float4* __restrict__ refb,
    const int4* __restrict__ ma, const int4* __restrict__ mb)
{
    __shared__ unsigned int sh[NHIST * NB];   // hists; tail: 24 integer cumsums
    __shared__ unsigned s_tots[12], s_tott[12];
    __shared__ int lutA[32], lutB[32];
    __shared__ int s_last;

    const int tid  = threadIdx.x;
    const int lane = tid & 31;
    const int wid  = tid >> 5;     // 16 warps

    for (int i = tid; i < NHIST * NB; i += 512) sh[i] = 0u;
    if (tid < 32) { lutA[tid] = c_lutA[tid]; lutB[tid] = c_lutB[tid]; }
    __syncthreads();

    int stride = gridDim.x * 512;
    for (int q = blockIdx.x * 512 + tid; q < NQ; q += stride) {
        int4   a4 = ma[q],  b4 = mb[q];
        float4 f0 = fake[q], f1 = fake[q + NQ], f2 = fake[q + 2 * NQ];
        float4 r0 = refb[q], r1 = refb[q + NQ], r2 = refb[q + 2 * NQ];
        hist_px(a4.x, b4.x, f0.x, f1.x, f2.x, r0.x, r1.x, r2.x, lutA, lutB, sh);
        hist_px(a4.y, b4.y, f0.y, f1.y, f2.y, r0.y, r1.y, r2.y, lutA, lutB, sh);
        hist_px(a4.z, b4.z, f0.z, f1.z, f2.z, r0.z, r1.z, r2.z, lutA, lutB, sh);
        hist_px(a4.w, b4.w, f0.w, f1.w, f2.w, r0.w, r1.w, r2.w, lutA, lutB, sh);
    }
    __syncthreads();
    for (int i = tid; i < NHIST * NB; i += 512) {
        unsigned v = sh[i];
        if (v) atomicAdd(&g_hist[i], v);
    }
    __syncthreads();

    // ---- ticket: last block to flush builds the tables (everything is in L2)
    if (tid == 0) {
        __threadfence();
        unsigned t = atomicAdd(&g_tick1, 1u);
        s_last = (t == (unsigned)(gridDim.x - 1)) ? 1 : 0;
    }
    __syncthreads();
    if (!s_last) return;

    // ---- phase A: 24 integer cumsums, warp-per-(table,side); zero g_hist as we go
    unsigned* smA = sh;                 // [12*NB] src cumsums
    unsigned* smB = sh + 12 * NB;       // [12*NB] tar cumsums
    for (int task = wid; task < 24; task += 16) {
        int rc = task >> 1, side = task & 1;    // rc = region*3 + c
        int region = rc / 3, c = rc - region * 3;
        int hbase = (region * 6 + side * 3 + c) * NB;

        unsigned v[8];
        #pragma unroll
        for (int k = 0; k < 8; k++) {
            v[k] = __ldcg(&g_hist[hbase + k * 32 + lane]);   // L2 (bypass L1)
            g_hist[hbase + k * 32 + lane] = 0u;              // self-clean for replay
        }
        #pragma unroll
        for (int k = 0; k < 8; k++) {
            unsigned x = v[k];
            #pragma unroll
            for (int off = 1; off < 32; off <<= 1) {
                unsigned y = __shfl_up_sync(0xffffffffu, x, off);
                if (lane >= off) x += y;
            }
            v[k] = x;
        }
        unsigned seg[8];
        #pragma unroll
        for (int k = 0; k < 8; k++)
            seg[k] = __shfl_sync(0xffffffffu, v[k], 31);

        unsigned* dst = (side ? smB : smA) + rc * NB;
        unsigned carry = 0;
        #pragma unroll
        for (int k = 0; k < 8; k++) {
            dst[k * 32 + lane] = v[k] + carry;
            carry += seg[k];
        }
        if (lane == 0) {
            if (side) s_tott[rc] = carry; else s_tots[rc] = carry;
        }
    }
    __syncthreads();

    // ---- phase B: exact integer binary lower-bound; 2 tables per round
    // cd[i] >= ca[j]  <=>  cs_cum[i]*tott >= ct_cum[j]*tots   (u64, exact)
    #pragma unroll
    for (int round = 0; round < 6; round++) {
        int r = round * 2 + (tid >> 8);         // 512 threads -> 2 tables
        int bin = tid & 255;
        const unsigned* ca = smB + r * NB;
        unsigned long long tots = s_tots[r];
        unsigned long long lhs  = (unsigned long long)smA[r * NB + bin] * s_tott[r];
        int lo = 1, hi = 255;
        #pragma unroll
        for (int s = 0; s < 8; s++) {
            int mid = (lo + hi) >> 1;
            if ((unsigned long long)ca[mid] * tots >= lhs) hi = mid; else lo = mid + 1;
        }
        bool found = (lhs >= (unsigned long long)ca[lo - 1] * tots)
                  && (lhs <= (unsigned long long)ca[lo]     * tots);
        int t = found ? lo : bin;
        if (bin == 0)   t = 0;
        if (bin == 255) t = 255;
        g_tables[r * NB + bin] = (float)t;
    }

    if (tid == 0) g_tick1 = 0u;   // reset for next replay (sole surviving block)
}

// ---------------------------------------------------------------- K2: loss (+ finalize)
__device__ __forceinline__ float loss_px(int la, float fa, float fb, float fc,
                                         const int* lutA, const float* tbl)
{
    int sbase = ((lutA[la] & 0xFFFF) - 1) >> 1;   // src hist base/2 == region*3*NB
    float s = 0.0f;
    if (sbase >= 0) {
        const float* tb = tbl + sbase;
        float v0 = sat01(fa) * 255.0f;
        float v1 = sat01(fb) * 255.0f;
        float v2 = sat01(fc) * 255.0f;
        int i0 = min(floor_pos(v0), 255);
        int i1 = min(floor_pos(v1), 255);
        int i2 = min(floor_pos(v2), 255);
        s = fabsf(v0 - tb[i0]) + fabsf(v1 - tb[NB + i1]) + fabsf(v2 - tb[2 * NB + i2]);
    }
    return s;
}

__global__ void __launch_bounds__(256) loss_kernel(
    const float4* __restrict__ fake, const int4* __restrict__ ma, float* out)
{
    __shared__ float tbl[12 * NB];
    __shared__ int lutA[32];
    __shared__ float wsum[8];

    const int tid = threadIdx.x;
    for (int i = tid; i < 12 * NB; i += 256) tbl[i] = g_tables[i];
    if (tid < 32) lutA[tid] = c_lutA[tid];
    __syncthreads();

    float acc = 0.0f;
    int stride = gridDim.x * 256;
    for (int q = blockIdx.x * 256 + tid; q < NQ; q += stride) {
        int4   a4 = ma[q];
        float4 f0 = fake[q], f1 = fake[q + NQ], f2 = fake[q + 2 * NQ];
        acc += loss_px(a4.x, f0.x, f1.x, f2.x, lutA, tbl);
        acc += loss_px(a4.y, f0.y, f1.y, f2.y, lutA, tbl);
        acc += loss_px(a4.z, f0.z, f1.z, f2.z, lutA, tbl);
        acc += loss_px(a4.w, f0.w, f1.w, f2.w, lutA, tbl);
    }

    #pragma unroll
    for (int off = 16; off > 0; off >>= 1)
        acc += __shfl_down_sync(0xffffffffu, acc, off);
    int lane = tid & 31, wid = tid >> 5;
    if (lane == 0) wsum[wid] = acc;
    __syncthreads();
    if (tid == 0) {
        float s = 0.0f;
        #pragma unroll
        for (int i = 0; i < 8; i++) s += wsum[i];
        atomicAdd(&g_acc, (double)s);
        __threadfence();
        unsigned t = atomicAdd(&g_tick2, 1u);
        if (t == (unsigned)(gridDim.x - 1)) {
            double total = *((volatile double*)&g_acc);
            out[0] = (float)(total * (0.1 / 12582912.0));  // 0.1/(3*H*W)
            g_acc = 0.0;
            g_tick2 = 0u;
        }
    }
}

// ---------------------------------------------------------------- launch
extern "C" void kernel_launch(void* const* d_in, const int* in_sizes, int n_in,
                              void* d_out, int out_size)
{
    (void)in_sizes; (void)n_in; (void)out_size;
    const float4* fake = (const float4*)d_in[0];
    const float4* refb = (const float4*)d_in[1];
    const int4*   ma   = (const int4*)d_in[2];
    const int4*   mb   = (const int4*)d_in[3];
    float* out = (float*)d_out;

    hist_kernel<<<296, 512>>>(fake, refb, ma, mb);
    loss_kernel<<<LOSS_GRID, 256>>>(fake, ma, out);
}